// round 6
// baseline (speedup 1.0000x reference)
#include <cuda_runtime.h>
#include <cuda_bf16.h>
#include <cfloat>
#include <cstdint>

// Problem shape (fixed by the dataset)
#define B_Q 2048
#define N_S 32768
#define D_K 256
#define N_CLS 100

#define BM 128
#define BN 128
#define BK 8
#define NCHUNK 2048              // support rows per blockIdx.y
#define NCHUNKS (N_S / NCHUNK)   // 16

// Scratch (device globals: allocation-free contract)
__device__ float g_s2[N_S];
__device__ float g_pv[B_Q * NCHUNKS];
__device__ int   g_pi[B_Q * NCHUNKS];

// ---------------------------------------------------------------------------
// Kernel 1: s2[n] = sum_d sup[n][d]^2   (warp per row, coalesced float4)
// ---------------------------------------------------------------------------
__global__ void s2_kernel(const float* __restrict__ sup) {
    int warp = (blockIdx.x * blockDim.x + threadIdx.x) >> 5;
    int lane = threadIdx.x & 31;
    if (warp >= N_S) return;
    const float* row = sup + (size_t)warp * D_K;
    float4 a = ((const float4*)row)[lane];
    float4 b = ((const float4*)row)[lane + 32];
    float s = a.x*a.x + a.y*a.y + a.z*a.z + a.w*a.w
            + b.x*b.x + b.y*b.y + b.z*b.z + b.w*b.w;
    #pragma unroll
    for (int off = 16; off > 0; off >>= 1)
        s += __shfl_down_sync(0xffffffffu, s, off);
    if (lane == 0) g_s2[warp] = s;
}

// ---------------------------------------------------------------------------
// Kernel 2: fused tiled GEMM (x . sup^T) + running argmin of s2 - 2*dot
// grid: (B/BM = 16, NCHUNKS = 16), 256 threads, 8x8 per-thread tile
// ---------------------------------------------------------------------------
__global__ __launch_bounds__(256, 2)
void knn_main_kernel(const float* __restrict__ x, const float* __restrict__ sup) {
    __shared__ float As[BK][BM];
    __shared__ float Bs[BK][BN];
    __shared__ float rv[BM][16];
    __shared__ int   ri[BM][16];

    const int tid = threadIdx.x;
    const int tx = tid & 15;        // n direction (16)
    const int ty = tid >> 4;        // m direction (16)
    const int m0 = blockIdx.x * BM;
    const int n0 = blockIdx.y * NCHUNK;

    const int lr = tid >> 1;          // 0..127  (row within tile for loads)
    const int lc = (tid & 1) * 4;     // 0 or 4  (k sub-offset for float4)

    float bestV[8];
    int   bestI[8];
    #pragma unroll
    for (int i = 0; i < 8; i++) { bestV[i] = FLT_MAX; bestI[i] = 0; }

    for (int nt = 0; nt < NCHUNK; nt += BN) {
        const float* supTile = sup + (size_t)(n0 + nt) * D_K;
        float acc[8][8];
        #pragma unroll
        for (int i = 0; i < 8; i++)
            #pragma unroll
            for (int j = 0; j < 8; j++) acc[i][j] = 0.f;

        for (int k0 = 0; k0 < D_K; k0 += BK) {
            float4 av = *(const float4*)(x + (size_t)(m0 + lr) * D_K + k0 + lc);
            As[lc + 0][lr] = av.x;
            As[lc + 1][lr] = av.y;
            As[lc + 2][lr] = av.z;
            As[lc + 3][lr] = av.w;
            float4 bv = *(const float4*)(supTile + (size_t)lr * D_K + k0 + lc);
            Bs[lc + 0][lr] = bv.x;
            Bs[lc + 1][lr] = bv.y;
            Bs[lc + 2][lr] = bv.z;
            Bs[lc + 3][lr] = bv.w;
            __syncthreads();

            #pragma unroll
            for (int k = 0; k < BK; k++) {
                float a[8], b[8];
                *(float4*)(a)     = *(const float4*)&As[k][ty * 8];
                *(float4*)(a + 4) = *(const float4*)&As[k][ty * 8 + 4];
                *(float4*)(b)     = *(const float4*)&Bs[k][tx * 8];
                *(float4*)(b + 4) = *(const float4*)&Bs[k][tx * 8 + 4];
                #pragma unroll
                for (int i = 0; i < 8; i++)
                    #pragma unroll
                    for (int j = 0; j < 8; j++)
                        acc[i][j] = fmaf(a[i], b[j], acc[i][j]);
            }
            __syncthreads();
        }

        #pragma unroll
        for (int j = 0; j < 8; j++) {
            int n = n0 + nt + tx * 8 + j;
            float s2n = g_s2[n];
            #pragma unroll
            for (int i = 0; i < 8; i++) {
                float sc = fmaf(-2.0f, acc[i][j], s2n);
                if (sc < bestV[i]) { bestV[i] = sc; bestI[i] = n; }
            }
        }
    }

    #pragma unroll
    for (int i = 0; i < 8; i++) {
        rv[ty * 8 + i][tx] = bestV[i];
        ri[ty * 8 + i][tx] = bestI[i];
    }
    __syncthreads();

    if (tid < BM) {
        float bv = rv[tid][0];
        int   bi = ri[tid][0];
        #pragma unroll
        for (int t = 1; t < 16; t++) {
            float v = rv[tid][t];
            int   iidx = ri[tid][t];
            if (v < bv || (v == bv && iidx < bi)) { bv = v; bi = iidx; }
        }
        int q = m0 + tid;
        g_pv[q * NCHUNKS + blockIdx.y] = bv;
        g_pi[q * NCHUNKS + blockIdx.y] = bi;
    }
}

// ---------------------------------------------------------------------------
// Kernel 3: final reduce over NCHUNKS partials + label gather + one-hot write.
//
// OUTPUT IS WRITTEN AS FLOAT32 (1.0f / 0.0f). Theory: the harness's
// __output__ dtype is float32; writing int 1s reads back as denormals ~ 0,
// which exactly reproduces the observed rel_err == 1.000000 invariant.
//
// Label storage detection (int64 vs int32): for little-endian int64 labels in
// [0,100), every odd 32-bit word is 0; OR over the first 32 entries decides.
// ---------------------------------------------------------------------------
__global__ void finalize_kernel(const int* __restrict__ lab32,
                                float* __restrict__ out) {
    __shared__ int s_lbl;
    const int b = blockIdx.x;
    if (threadIdx.x == 0) {
        float bv = g_pv[b * NCHUNKS];
        int   bi = g_pi[b * NCHUNKS];
        #pragma unroll
        for (int t = 1; t < NCHUNKS; t++) {
            float v = g_pv[b * NCHUNKS + t];
            int   iidx = g_pi[b * NCHUNKS + t];
            if (v < bv || (v == bv && iidx < bi)) { bv = v; bi = iidx; }
        }
        int hiOr = 0;
        #pragma unroll
        for (int w = 1; w < 64; w += 2) hiOr |= lab32[w];
        s_lbl = (hiOr == 0) ? lab32[2 * bi]   // int64 storage (low word)
                            : lab32[bi];      // int32 storage
    }
    __syncthreads();
    int lbl = s_lbl;
    for (int c = threadIdx.x; c < N_CLS; c += blockDim.x)
        out[(size_t)b * N_CLS + c] = (c == lbl) ? 1.0f : 0.0f;
}

// ---------------------------------------------------------------------------
// Host: bind inputs by size, matching BOTH element-count and byte-count
// interpretations of in_sizes (all role sizes are pairwise distinct under
// both). Falls back to positional (reference dict order) if nothing matches.
// ---------------------------------------------------------------------------
extern "C" void kernel_launch(void* const* d_in, const int* in_sizes, int n_in,
                              void* d_out, int out_size) {
    const float* x     = nullptr;
    const float* sup   = nullptr;
    const int*   lab32 = nullptr;

    for (int i = 0; i < n_in; i++) {
        long long sz = in_sizes[i];
        // x: 524288 elems | 2097152 bytes
        if (sz == 524288LL || sz == 2097152LL)         x     = (const float*)d_in[i];
        // support: 8388608 elems | 33554432 bytes
        else if (sz == 8388608LL || sz == 33554432LL)  sup   = (const float*)d_in[i];
        // labels: 32768/65536 elems | 131072/262144 bytes
        else if (sz == 32768LL || sz == 65536LL ||
                 sz == 131072LL || sz == 262144LL)     lab32 = (const int*)d_in[i];
        // tiny (1..8): num_classes scalar -> ignored (compile-time constant)
    }
    if (!x)     x     = (const float*)d_in[0];
    if (!sup)   sup   = (const float*)d_in[1];
    if (!lab32) lab32 = (const int*)d_in[2];

    float* out = (float*)d_out;

    s2_kernel<<<4096, 256>>>(sup);

    dim3 grid(B_Q / BM, NCHUNKS);   // 16 x 16
    knn_main_kernel<<<grid, 256>>>(x, sup);

    finalize_kernel<<<B_Q, 128>>>(lab32, out);
}

// round 8
// speedup vs baseline: 1.8497x; 1.8497x over previous
#include <cuda_runtime.h>
#include <cuda_bf16.h>
#include <cfloat>
#include <cstdint>

// Problem shape (fixed by the dataset)
#define B_Q 2048
#define N_S 32768
#define D_K 256
#define N_CLS 100

// bf16 3-way split -> 6 K-segments -> single GEMM with K' = 1536
#define KP (D_K * 6)               // 1536
#define KCHUNK 64                  // bf16 per chunk = 128 B rows
#define NKCH (KP / KCHUNK)         // 24
#define TILE_M 128
#define TILE_N 128
#define GRID_M (B_Q / TILE_M)      // 16
#define GRID_N (N_S / TILE_N)      // 256
#define STAGES 3
#define STAGE_BYTES 32768          // A 16KB + B 16KB
#define ROWB 128                   // bytes per SMEM row (64 bf16)
#define GROWB (KP * 2)             // 3072 bytes per global row

// ---- device global scratch (allocation-free contract) ----
__device__ __nv_bfloat16 g_A[(size_t)B_Q * KP];   // 6.3 MB
__device__ __nv_bfloat16 g_B[(size_t)N_S * KP];   // 100.7 MB
__device__ float g_s2[N_S];
__device__ float g_pv[(size_t)B_Q * GRID_N];      // 2 MB
__device__ int   g_pi[(size_t)B_Q * GRID_N];      // 2 MB

// ---------------------------------------------------------------------------
// helpers
// ---------------------------------------------------------------------------
__device__ __forceinline__ uint32_t smem_u32(const void* p) {
    uint32_t a;
    asm("{ .reg .u64 t; cvta.to.shared.u64 t, %1; cvt.u32.u64 %0, t; }"
        : "=r"(a) : "l"(p));
    return a;
}
__device__ __forceinline__ void cp16(uint32_t dst, const void* src) {
    asm volatile("cp.async.cg.shared.global [%0], [%1], 16;"
                 :: "r"(dst), "l"(src) : "memory");
}
__device__ __forceinline__ void cp_commit() {
    asm volatile("cp.async.commit_group;" ::: "memory");
}
template <int N> __device__ __forceinline__ void cp_wait() {
    asm volatile("cp.async.wait_group %0;" :: "n"(N) : "memory");
}
__device__ __forceinline__ void ldsm4(uint32_t& r0, uint32_t& r1,
                                      uint32_t& r2, uint32_t& r3, uint32_t a) {
    asm volatile("ldmatrix.sync.aligned.m8n8.x4.shared.b16 {%0,%1,%2,%3}, [%4];"
                 : "=r"(r0), "=r"(r1), "=r"(r2), "=r"(r3) : "r"(a));
}
__device__ __forceinline__ void mma16816(float* c, const uint32_t* a,
                                         const uint32_t* b) {
    asm volatile(
        "mma.sync.aligned.m16n8k16.row.col.f32.bf16.bf16.f32 "
        "{%0,%1,%2,%3}, {%4,%5,%6,%7}, {%8,%9}, {%0,%1,%2,%3};"
        : "+f"(c[0]), "+f"(c[1]), "+f"(c[2]), "+f"(c[3])
        : "r"(a[0]), "r"(a[1]), "r"(a[2]), "r"(a[3]), "r"(b[0]), "r"(b[1]));
}
// SW128 swizzle for 128B rows: chunk index (bits 4-6) XOR (row & 7)
__device__ __forceinline__ uint32_t swz(uint32_t row, uint32_t colb) {
    return row * ROWB + (colb ^ ((row & 7u) << 4));
}

// ---------------------------------------------------------------------------
// Prologue 1: split x rows into 3 bf16 terms; A segments [a1,a2,a3,a1,a1,a2]
// ---------------------------------------------------------------------------
__global__ void convert_x_kernel(const float* __restrict__ x) {
    int q = blockIdx.x, d = threadIdx.x;
    float v = x[(size_t)q * D_K + d];
    __nv_bfloat16 a1 = __float2bfloat16(v);
    float r1 = v - __bfloat162float(a1);
    __nv_bfloat16 a2 = __float2bfloat16(r1);
    float r2 = r1 - __bfloat162float(a2);
    __nv_bfloat16 a3 = __float2bfloat16(r2);
    __nv_bfloat16* A = g_A + (size_t)q * KP;
    A[0 * D_K + d] = a1; A[1 * D_K + d] = a2; A[2 * D_K + d] = a3;
    A[3 * D_K + d] = a1; A[4 * D_K + d] = a1; A[5 * D_K + d] = a2;
}

// ---------------------------------------------------------------------------
// Prologue 2: split support rows; B segments [b1,b1,b1,b2,b3,b2]; fused s2
// ---------------------------------------------------------------------------
__global__ void convert_s_kernel(const float* __restrict__ sup) {
    __shared__ float red[8];
    int n = blockIdx.x, d = threadIdx.x;
    float v = sup[(size_t)n * D_K + d];
    __nv_bfloat16 b1 = __float2bfloat16(v);
    float r1 = v - __bfloat162float(b1);
    __nv_bfloat16 b2 = __float2bfloat16(r1);
    float r2 = r1 - __bfloat162float(b2);
    __nv_bfloat16 b3 = __float2bfloat16(r2);
    __nv_bfloat16* Bp = g_B + (size_t)n * KP;
    Bp[0 * D_K + d] = b1; Bp[1 * D_K + d] = b1; Bp[2 * D_K + d] = b1;
    Bp[3 * D_K + d] = b2; Bp[4 * D_K + d] = b3; Bp[5 * D_K + d] = b2;
    float s = v * v;
    #pragma unroll
    for (int off = 16; off > 0; off >>= 1) s += __shfl_down_sync(0xffffffffu, s, off);
    if ((d & 31) == 0) red[d >> 5] = s;
    __syncthreads();
    if (d == 0) {
        float t = 0.f;
        #pragma unroll
        for (int i = 0; i < 8; i++) t += red[i];
        g_s2[n] = t;
    }
}

// ---------------------------------------------------------------------------
// Main: HMMA (mma.sync bf16) GEMM M128 x N128 x K1536 fused with argmin
// grid (GRID_N=256, GRID_M=16), 256 threads (8 warps, 4x2 -> warp 32x64)
// ---------------------------------------------------------------------------
__global__ __launch_bounds__(256)
void knn_mma_kernel() {
    extern __shared__ char smem[];
    const uint32_t sb = smem_u32(smem);
    __shared__ float s_s2[TILE_N];
    __shared__ float spv[TILE_M][2];
    __shared__ int   spi[TILE_M][2];

    const int tid = threadIdx.x, wid = tid >> 5, lane = tid & 31;
    const int warp_m = wid & 3, warp_n = wid >> 2;
    const int n0 = blockIdx.x * TILE_N, m0 = blockIdx.y * TILE_M;

    if (tid < TILE_N) s_s2[tid] = g_s2[n0 + tid];

    const char* gA = (const char*)g_A + (size_t)m0 * GROWB;
    const char* gB = (const char*)g_B + (size_t)n0 * GROWB;

    // -- async load of one K-chunk into stage buffer (A 16KB + B 16KB) --
    auto load_chunk = [&](int kc, int stg) {
        uint32_t sA = sb + stg * STAGE_BYTES;
        uint32_t sB = sA + 16384;
        size_t colb = (size_t)kc * ROWB;
        #pragma unroll
        for (int i = 0; i < 4; i++) {
            int idx = tid + i * 256;
            int r = idx >> 3, p = (idx & 7) * 16;
            cp16(sA + swz(r, p), gA + (size_t)r * GROWB + colb + p);
        }
        #pragma unroll
        for (int i = 0; i < 4; i++) {
            int idx = tid + i * 256;
            int r = idx >> 3, p = (idx & 7) * 16;
            cp16(sB + swz(r, p), gB + (size_t)r * GROWB + colb + p);
        }
        cp_commit();
    };

    float acc[2][8][4];
    #pragma unroll
    for (int mt = 0; mt < 2; mt++)
        #pragma unroll
        for (int nb = 0; nb < 8; nb++)
            #pragma unroll
            for (int i = 0; i < 4; i++) acc[mt][nb][i] = 0.f;

    // per-lane fixed row/col pieces for ldmatrix addressing
    const uint32_t a_row = (uint32_t)(warp_m * 32 + (lane & 15));
    const uint32_t a_sub = (uint32_t)((lane >> 4) * 16);
    const uint32_t b_row = (uint32_t)(warp_n * 64 + (lane & 7) + ((lane >> 4) << 3));
    const uint32_t b_sub = (uint32_t)(((lane >> 3) & 1) * 16);

    load_chunk(0, 0);
    load_chunk(1, 1);

    for (int k = 0; k < NKCH; k++) {
        cp_wait<1>();
        __syncthreads();
        if (k + 2 < NKCH) load_chunk(k + 2, (k + 2) % STAGES);

        uint32_t sA = sb + (k % STAGES) * STAGE_BYTES;
        uint32_t sB = sA + 16384;
        #pragma unroll
        for (int ks = 0; ks < 4; ks++) {
            uint32_t colA = (uint32_t)(ks * 32) + a_sub;
            uint32_t colB = (uint32_t)(ks * 32) + b_sub;
            uint32_t a[2][4], b[8][2];
            #pragma unroll
            for (int mt = 0; mt < 2; mt++)
                ldsm4(a[mt][0], a[mt][1], a[mt][2], a[mt][3],
                      sA + swz(a_row + mt * 16, colA));
            #pragma unroll
            for (int nb2 = 0; nb2 < 4; nb2++)
                ldsm4(b[nb2 * 2][0], b[nb2 * 2][1], b[nb2 * 2 + 1][0], b[nb2 * 2 + 1][1],
                      sB + swz(b_row + nb2 * 16, colB));
            #pragma unroll
            for (int mt = 0; mt < 2; mt++)
                #pragma unroll
                for (int nb = 0; nb < 8; nb++)
                    mma16816(acc[mt][nb], a[mt], b[nb]);
        }
        __syncthreads();   // all warps done reading stage before overwrite
    }

    // -- fused epilogue: score = s2[n] - 2*dot, running argmin --
    float bv[2][2]; int bi[2][2];
    #pragma unroll
    for (int mt = 0; mt < 2; mt++)
        #pragma unroll
        for (int rh = 0; rh < 2; rh++) { bv[mt][rh] = FLT_MAX; bi[mt][rh] = 0; }

    #pragma unroll
    for (int mt = 0; mt < 2; mt++)
        #pragma unroll
        for (int rh = 0; rh < 2; rh++)
            #pragma unroll
            for (int nb = 0; nb < 8; nb++)
                #pragma unroll
                for (int c = 0; c < 2; c++) {
                    int col = warp_n * 64 + nb * 8 + 2 * (lane & 3) + c;
                    float sc = fmaf(-2.0f, acc[mt][nb][rh * 2 + c], s_s2[col]);
                    int n = n0 + col;
                    if (sc < bv[mt][rh]) { bv[mt][rh] = sc; bi[mt][rh] = n; }
                }

    // reduce across the 4 lanes sharing a row (lane bits 0-1 vary n)
    #pragma unroll
    for (int mt = 0; mt < 2; mt++)
        #pragma unroll
        for (int rh = 0; rh < 2; rh++) {
            float v = bv[mt][rh]; int ix = bi[mt][rh];
            #pragma unroll
            for (int msk = 1; msk <= 2; msk <<= 1) {
                float ov = __shfl_xor_sync(0xffffffffu, v, msk);
                int   oi = __shfl_xor_sync(0xffffffffu, ix, msk);
                if (ov < v || (ov == v && oi < ix)) { v = ov; ix = oi; }
            }
            if ((lane & 3) == 0) {
                int row = warp_m * 32 + mt * 16 + rh * 8 + (lane >> 2);
                spv[row][warp_n] = v;
                spi[row][warp_n] = ix;
            }
        }
    __syncthreads();

    if (tid < TILE_M) {
        float v0 = spv[tid][0], v1 = spv[tid][1];
        int   i0 = spi[tid][0], i1 = spi[tid][1];
        bool take1 = (v1 < v0) || (v1 == v0 && i1 < i0);
        g_pv[(size_t)(m0 + tid) * GRID_N + blockIdx.x] = take1 ? v1 : v0;
        g_pi[(size_t)(m0 + tid) * GRID_N + blockIdx.x] = take1 ? i1 : i0;
    }
}

// ---------------------------------------------------------------------------
// Finalize: reduce GRID_N partials/query, gather label, write float one-hot
// ---------------------------------------------------------------------------
__global__ void finalize_kernel(const int* __restrict__ lab32,
                                float* __restrict__ out) {
    __shared__ float sv[256];
    __shared__ int   si[256];
    __shared__ int   s_lbl;
    const int b = blockIdx.x, t = threadIdx.x;
    sv[t] = g_pv[(size_t)b * GRID_N + t];
    si[t] = g_pi[(size_t)b * GRID_N + t];
    __syncthreads();
    #pragma unroll
    for (int s = 128; s > 0; s >>= 1) {
        if (t < s) {
            float v2 = sv[t + s]; int i2 = si[t + s];
            if (v2 < sv[t] || (v2 == sv[t] && i2 < si[t])) { sv[t] = v2; si[t] = i2; }
        }
        __syncthreads();
    }
    if (t == 0) {
        int bi = si[0];
        int hiOr = 0;                 // int64-vs-int32 label storage detection
        #pragma unroll
        for (int w = 1; w < 64; w += 2) hiOr |= lab32[w];
        s_lbl = (hiOr == 0) ? lab32[2 * bi] : lab32[bi];
    }
    __syncthreads();
    if (t < N_CLS) out[(size_t)b * N_CLS + t] = (t == s_lbl) ? 1.0f : 0.0f;
}

// ---------------------------------------------------------------------------
extern "C" void kernel_launch(void* const* d_in, const int* in_sizes, int n_in,
                              void* d_out, int out_size) {
    const float* x     = nullptr;
    const float* sup   = nullptr;
    const int*   lab32 = nullptr;
    for (int i = 0; i < n_in; i++) {
        long long sz = in_sizes[i];
        if (sz == 524288LL || sz == 2097152LL)         x     = (const float*)d_in[i];
        else if (sz == 8388608LL || sz == 33554432LL)  sup   = (const float*)d_in[i];
        else if (sz == 32768LL || sz == 65536LL ||
                 sz == 131072LL || sz == 262144LL)     lab32 = (const int*)d_in[i];
    }
    if (!x)     x     = (const float*)d_in[0];
    if (!sup)   sup   = (const float*)d_in[1];
    if (!lab32) lab32 = (const int*)d_in[2];
    float* out = (float*)d_out;

    static bool attr_set = false;
    if (!attr_set) {
        cudaFuncSetAttribute(knn_mma_kernel,
                             cudaFuncAttributeMaxDynamicSharedMemorySize,
                             STAGES * STAGE_BYTES);
        attr_set = true;
    }

    convert_x_kernel<<<B_Q, D_K>>>(x);
    convert_s_kernel<<<N_S, D_K>>>(sup);

    dim3 grid(GRID_N, GRID_M);   // 256 x 16
    knn_mma_kernel<<<grid, 256, STAGES * STAGE_BYTES>>>();

    finalize_kernel<<<B_Q, 256>>>(lab32, out);
}

// round 9
// speedup vs baseline: 3.1066x; 1.6795x over previous
#include <cuda_runtime.h>
#include <cuda_bf16.h>
#include <cfloat>
#include <cstdint>

// Problem shape (fixed by the dataset)
#define B_Q 2048
#define N_S 32768
#define D_K 256
#define N_CLS 100

// bf16 2-way split, 3 products -> single GEMM with K' = 768
#define KP (D_K * 3)               // 768
#define KCHUNK 64                  // bf16 per chunk = 128 B rows
#define NKCH (KP / KCHUNK)         // 12
#define TILE_M 128
#define TILE_N 256
#define GRID_M (B_Q / TILE_M)      // 16
#define GRID_N (N_S / TILE_N)      // 128
#define STAGES 3
#define A_STAGE 16384              // 128 x 128B
#define B_STAGE 32768              // 256 x 128B
#define STAGE_BYTES (A_STAGE + B_STAGE)   // 48 KB
#define ROWB 128                   // bytes per SMEM row (64 bf16)
#define GROWB (KP * 2)             // 1536 bytes per global row

// ---- device global scratch (allocation-free contract) ----
__device__ __nv_bfloat16 g_A[(size_t)B_Q * KP];   // 3.1 MB
__device__ __nv_bfloat16 g_B[(size_t)N_S * KP];   // 50.3 MB
__device__ float g_s2[N_S];
__device__ float g_pv[(size_t)B_Q * GRID_N];      // 1 MB
__device__ int   g_pi[(size_t)B_Q * GRID_N];      // 1 MB

// ---------------------------------------------------------------------------
// helpers
// ---------------------------------------------------------------------------
__device__ __forceinline__ uint32_t smem_u32(const void* p) {
    uint32_t a;
    asm("{ .reg .u64 t; cvta.to.shared.u64 t, %1; cvt.u32.u64 %0, t; }"
        : "=r"(a) : "l"(p));
    return a;
}
__device__ __forceinline__ void cp16(uint32_t dst, const void* src) {
    asm volatile("cp.async.cg.shared.global [%0], [%1], 16;"
                 :: "r"(dst), "l"(src) : "memory");
}
__device__ __forceinline__ void cp_commit() {
    asm volatile("cp.async.commit_group;" ::: "memory");
}
template <int N> __device__ __forceinline__ void cp_wait() {
    asm volatile("cp.async.wait_group %0;" :: "n"(N) : "memory");
}
__device__ __forceinline__ void ldsm4(uint32_t& r0, uint32_t& r1,
                                      uint32_t& r2, uint32_t& r3, uint32_t a) {
    asm volatile("ldmatrix.sync.aligned.m8n8.x4.shared.b16 {%0,%1,%2,%3}, [%4];"
                 : "=r"(r0), "=r"(r1), "=r"(r2), "=r"(r3) : "r"(a));
}
__device__ __forceinline__ void mma16816(float* c, const uint32_t* a,
                                         const uint32_t* b) {
    asm volatile(
        "mma.sync.aligned.m16n8k16.row.col.f32.bf16.bf16.f32 "
        "{%0,%1,%2,%3}, {%4,%5,%6,%7}, {%8,%9}, {%0,%1,%2,%3};"
        : "+f"(c[0]), "+f"(c[1]), "+f"(c[2]), "+f"(c[3])
        : "r"(a[0]), "r"(a[1]), "r"(a[2]), "r"(a[3]), "r"(b[0]), "r"(b[1]));
}
// SW128 swizzle for 128B rows
__device__ __forceinline__ uint32_t swz(uint32_t row, uint32_t colb) {
    return row * ROWB + (colb ^ ((row & 7u) << 4));
}

// ---------------------------------------------------------------------------
// Prologue 1: split x rows into 2 bf16 terms; A segments [a1, a2, a1]
// ---------------------------------------------------------------------------
__global__ void convert_x_kernel(const float* __restrict__ x) {
    int q = blockIdx.x, d = threadIdx.x;
    float v = x[(size_t)q * D_K + d];
    __nv_bfloat16 a1 = __float2bfloat16(v);
    float r1 = v - __bfloat162float(a1);
    __nv_bfloat16 a2 = __float2bfloat16(r1);
    __nv_bfloat16* A = g_A + (size_t)q * KP;
    A[0 * D_K + d] = a1; A[1 * D_K + d] = a2; A[2 * D_K + d] = a1;
}

// ---------------------------------------------------------------------------
// Prologue 2: split support rows; B segments [b1, b1, b2]; fused s2
// ---------------------------------------------------------------------------
__global__ void convert_s_kernel(const float* __restrict__ sup) {
    __shared__ float red[8];
    int n = blockIdx.x, d = threadIdx.x;
    float v = sup[(size_t)n * D_K + d];
    __nv_bfloat16 b1 = __float2bfloat16(v);
    float r1 = v - __bfloat162float(b1);
    __nv_bfloat16 b2 = __float2bfloat16(r1);
    __nv_bfloat16* Bp = g_B + (size_t)n * KP;
    Bp[0 * D_K + d] = b1; Bp[1 * D_K + d] = b1; Bp[2 * D_K + d] = b2;
    float s = v * v;
    #pragma unroll
    for (int off = 16; off > 0; off >>= 1) s += __shfl_down_sync(0xffffffffu, s, off);
    if ((d & 31) == 0) red[d >> 5] = s;
    __syncthreads();
    if (d == 0) {
        float t = 0.f;
        #pragma unroll
        for (int i = 0; i < 8; i++) t += red[i];
        g_s2[n] = t;
    }
}

// ---------------------------------------------------------------------------
// Main: HMMA (mma.sync bf16) GEMM M128 x N256 x K768 fused with argmin
// grid (GRID_N=128, GRID_M=16), 256 threads (8 warps 4x2 -> warp 32x128)
// ---------------------------------------------------------------------------
__global__ __launch_bounds__(256)
void knn_mma_kernel() {
    extern __shared__ char smem[];
    const uint32_t sb = smem_u32(smem);
    __shared__ float s_s2[TILE_N];
    __shared__ float spv[TILE_M][2];
    __shared__ int   spi[TILE_M][2];

    const int tid = threadIdx.x, wid = tid >> 5, lane = tid & 31;
    const int warp_m = wid & 3, warp_n = wid >> 2;
    const int n0 = blockIdx.x * TILE_N, m0 = blockIdx.y * TILE_M;

    if (tid < TILE_N) s_s2[tid] = g_s2[n0 + tid];

    const char* gA = (const char*)g_A + (size_t)m0 * GROWB;
    const char* gB = (const char*)g_B + (size_t)n0 * GROWB;

    // -- async load of one K-chunk into stage buffer (A 16KB + B 32KB) --
    auto load_chunk = [&](int kc, int stg) {
        uint32_t sA = sb + stg * STAGE_BYTES;
        uint32_t sB = sA + A_STAGE;
        size_t colb = (size_t)kc * ROWB;
        #pragma unroll
        for (int i = 0; i < 4; i++) {            // A: 128 rows x 8 x 16B
            int idx = tid + i * 256;
            int r = idx >> 3, p = (idx & 7) * 16;
            cp16(sA + swz(r, p), gA + (size_t)r * GROWB + colb + p);
        }
        #pragma unroll
        for (int i = 0; i < 8; i++) {            // B: 256 rows x 8 x 16B
            int idx = tid + i * 256;
            int r = idx >> 3, p = (idx & 7) * 16;
            cp16(sB + swz(r, p), gB + (size_t)r * GROWB + colb + p);
        }
        cp_commit();
    };

    float acc[2][16][4];
    #pragma unroll
    for (int mt = 0; mt < 2; mt++)
        #pragma unroll
        for (int nb = 0; nb < 16; nb++)
            #pragma unroll
            for (int i = 0; i < 4; i++) acc[mt][nb][i] = 0.f;

    // per-lane fixed row/col pieces for ldmatrix addressing
    const uint32_t a_row = (uint32_t)(warp_m * 32 + (lane & 15));
    const uint32_t a_sub = (uint32_t)((lane >> 4) * 16);
    const uint32_t b_row = (uint32_t)(warp_n * 128 + (lane & 7) + ((lane >> 4) << 3));
    const uint32_t b_sub = (uint32_t)(((lane >> 3) & 1) * 16);

    load_chunk(0, 0);
    load_chunk(1, 1);

    for (int k = 0; k < NKCH; k++) {
        cp_wait<1>();
        __syncthreads();
        if (k + 2 < NKCH) load_chunk(k + 2, (k + 2) % STAGES);

        uint32_t sA = sb + (k % STAGES) * STAGE_BYTES;
        uint32_t sB = sA + A_STAGE;
        #pragma unroll
        for (int ks = 0; ks < 4; ks++) {
            uint32_t colA = (uint32_t)(ks * 32) + a_sub;
            uint32_t colB = (uint32_t)(ks * 32) + b_sub;
            uint32_t a[2][4];
            #pragma unroll
            for (int mt = 0; mt < 2; mt++)
                ldsm4(a[mt][0], a[mt][1], a[mt][2], a[mt][3],
                      sA + swz(a_row + mt * 16, colA));
            // process B in two halves of 64 cols to bound live registers
            #pragma unroll
            for (int h = 0; h < 2; h++) {
                uint32_t b[8][2];
                #pragma unroll
                for (int nb2 = 0; nb2 < 4; nb2++)
                    ldsm4(b[nb2 * 2][0], b[nb2 * 2][1],
                          b[nb2 * 2 + 1][0], b[nb2 * 2 + 1][1],
                          sB + swz(b_row + h * 64 + nb2 * 16, colB));
                #pragma unroll
                for (int mt = 0; mt < 2; mt++)
                    #pragma unroll
                    for (int nb = 0; nb < 8; nb++)
                        mma16816(acc[mt][h * 8 + nb], a[mt], b[nb]);
            }
        }
        __syncthreads();   // all warps done reading stage before overwrite
    }

    // -- fused epilogue: score = s2[n] - 2*dot, running argmin --
    float bv[2][2]; int bi[2][2];
    #pragma unroll
    for (int mt = 0; mt < 2; mt++)
        #pragma unroll
        for (int rh = 0; rh < 2; rh++) { bv[mt][rh] = FLT_MAX; bi[mt][rh] = 0; }

    #pragma unroll
    for (int mt = 0; mt < 2; mt++)
        #pragma unroll
        for (int rh = 0; rh < 2; rh++)
            #pragma unroll
            for (int nb = 0; nb < 16; nb++)
                #pragma unroll
                for (int c = 0; c < 2; c++) {
                    int col = warp_n * 128 + nb * 8 + 2 * (lane & 3) + c;
                    float sc = fmaf(-2.0f, acc[mt][nb][rh * 2 + c], s_s2[col]);
                    int n = n0 + col;
                    if (sc < bv[mt][rh]) { bv[mt][rh] = sc; bi[mt][rh] = n; }
                }

    // reduce across the 4 lanes sharing a row (lane bits 0-1 vary n)
    #pragma unroll
    for (int mt = 0; mt < 2; mt++)
        #pragma unroll
        for (int rh = 0; rh < 2; rh++) {
            float v = bv[mt][rh]; int ix = bi[mt][rh];
            #pragma unroll
            for (int msk = 1; msk <= 2; msk <<= 1) {
                float ov = __shfl_xor_sync(0xffffffffu, v, msk);
                int   oi = __shfl_xor_sync(0xffffffffu, ix, msk);
                if (ov < v || (ov == v && oi < ix)) { v = ov; ix = oi; }
            }
            if ((lane & 3) == 0) {
                int row = warp_m * 32 + mt * 16 + rh * 8 + (lane >> 2);
                spv[row][warp_n] = v;
                spi[row][warp_n] = ix;
            }
        }
    __syncthreads();

    if (tid < TILE_M) {
        float v0 = spv[tid][0], v1 = spv[tid][1];
        int   i0 = spi[tid][0], i1 = spi[tid][1];
        bool take1 = (v1 < v0) || (v1 == v0 && i1 < i0);
        g_pv[(size_t)(m0 + tid) * GRID_N + blockIdx.x] = take1 ? v1 : v0;
        g_pi[(size_t)(m0 + tid) * GRID_N + blockIdx.x] = take1 ? i1 : i0;
    }
}

// ---------------------------------------------------------------------------
// Finalize: reduce GRID_N partials/query, gather label, write float one-hot
// ---------------------------------------------------------------------------
__global__ void finalize_kernel(const int* __restrict__ lab32,
                                float* __restrict__ out) {
    __shared__ float sv[GRID_N];
    __shared__ int   si[GRID_N];
    __shared__ int   s_lbl;
    const int b = blockIdx.x, t = threadIdx.x;
    sv[t] = g_pv[(size_t)b * GRID_N + t];
    si[t] = g_pi[(size_t)b * GRID_N + t];
    __syncthreads();
    #pragma unroll
    for (int s = GRID_N / 2; s > 0; s >>= 1) {
        if (t < s) {
            float v2 = sv[t + s]; int i2 = si[t + s];
            if (v2 < sv[t] || (v2 == sv[t] && i2 < si[t])) { sv[t] = v2; si[t] = i2; }
        }
        __syncthreads();
    }
    if (t == 0) {
        int bi = si[0];
        int hiOr = 0;                 // int64-vs-int32 label storage detection
        #pragma unroll
        for (int w = 1; w < 64; w += 2) hiOr |= lab32[w];
        s_lbl = (hiOr == 0) ? lab32[2 * bi] : lab32[bi];
    }
    __syncthreads();
    if (t < N_CLS) out[(size_t)b * N_CLS + t] = (t == s_lbl) ? 1.0f : 0.0f;
}

// ---------------------------------------------------------------------------
extern "C" void kernel_launch(void* const* d_in, const int* in_sizes, int n_in,
                              void* d_out, int out_size) {
    const float* x     = nullptr;
    const float* sup   = nullptr;
    const int*   lab32 = nullptr;
    for (int i = 0; i < n_in; i++) {
        long long sz = in_sizes[i];
        if (sz == 524288LL || sz == 2097152LL)         x     = (const float*)d_in[i];
        else if (sz == 8388608LL || sz == 33554432LL)  sup   = (const float*)d_in[i];
        else if (sz == 32768LL || sz == 65536LL ||
                 sz == 131072LL || sz == 262144LL)     lab32 = (const int*)d_in[i];
    }
    if (!x)     x     = (const float*)d_in[0];
    if (!sup)   sup   = (const float*)d_in[1];
    if (!lab32) lab32 = (const int*)d_in[2];
    float* out = (float*)d_out;

    static bool attr_set = false;
    if (!attr_set) {
        cudaFuncSetAttribute(knn_mma_kernel,
                             cudaFuncAttributeMaxDynamicSharedMemorySize,
                             STAGES * STAGE_BYTES);
        attr_set = true;
    }

    convert_x_kernel<<<B_Q, D_K>>>(x);
    convert_s_kernel<<<N_S, D_K>>>(sup);

    dim3 grid(GRID_N, GRID_M);   // 128 x 16
    knn_mma_kernel<<<grid, 256, STAGES * STAGE_BYTES>>>();

    finalize_kernel<<<B_Q, GRID_N>>>(lab32, out);
}

// round 11
// speedup vs baseline: 3.1329x; 1.0085x over previous
#include <cuda_runtime.h>
#include <cuda_bf16.h>
#include <cfloat>
#include <cstdint>

// Problem shape (fixed by the dataset)
#define B_Q 2048
#define N_S 32768
#define D_K 256
#define N_CLS 100

// bf16 2-way split, 3 products -> single GEMM with K' = 768
#define KP (D_K * 3)               // 768
#define NKCH (KP / 64)             // 12 K-chunks of 64 bf16
#define TILE_M 128
#define TILE_N 256
#define GRID_M (B_Q / TILE_M)      // 16
#define GRID_N (N_S / TILE_N)      // 128
#define NTHREADS 512
#define STAGES 4
#define A_STAGE 16384              // 128 x 128B
#define B_STAGE 32768              // 256 x 128B
#define STAGE_BYTES (A_STAGE + B_STAGE)   // 48 KB
#define ROWB 128                   // bytes per SMEM row (64 bf16)
#define GROWB (KP * 2)             // 1536 bytes per global row

// ---- device global scratch (allocation-free contract) ----
__device__ __nv_bfloat16 g_A[(size_t)B_Q * KP];   // 3.1 MB
__device__ __nv_bfloat16 g_B[(size_t)N_S * KP];   // 50.3 MB
__device__ float g_s2[N_S];
__device__ float g_pv[(size_t)B_Q * GRID_N];      // 1 MB
__device__ int   g_pi[(size_t)B_Q * GRID_N];      // 1 MB

// ---------------------------------------------------------------------------
// helpers
// ---------------------------------------------------------------------------
__device__ __forceinline__ uint32_t smem_u32(const void* p) {
    uint32_t a;
    asm("{ .reg .u64 t; cvta.to.shared.u64 t, %1; cvt.u32.u64 %0, t; }"
        : "=r"(a) : "l"(p));
    return a;
}
__device__ __forceinline__ void cp16(uint32_t dst, const void* src) {
    asm volatile("cp.async.cg.shared.global [%0], [%1], 16;"
                 :: "r"(dst), "l"(src) : "memory");
}
__device__ __forceinline__ void cp_commit() {
    asm volatile("cp.async.commit_group;" ::: "memory");
}
template <int N> __device__ __forceinline__ void cp_wait() {
    asm volatile("cp.async.wait_group %0;" :: "n"(N) : "memory");
}
__device__ __forceinline__ void ldsm4(uint32_t& r0, uint32_t& r1,
                                      uint32_t& r2, uint32_t& r3, uint32_t a) {
    asm volatile("ldmatrix.sync.aligned.m8n8.x4.shared.b16 {%0,%1,%2,%3}, [%4];"
                 : "=r"(r0), "=r"(r1), "=r"(r2), "=r"(r3) : "r"(a));
}
__device__ __forceinline__ void mma16816(float* c, const uint32_t* a,
                                         const uint32_t* b) {
    asm volatile(
        "mma.sync.aligned.m16n8k16.row.col.f32.bf16.bf16.f32 "
        "{%0,%1,%2,%3}, {%4,%5,%6,%7}, {%8,%9}, {%0,%1,%2,%3};"
        : "+f"(c[0]), "+f"(c[1]), "+f"(c[2]), "+f"(c[3])
        : "r"(a[0]), "r"(a[1]), "r"(a[2]), "r"(a[3]), "r"(b[0]), "r"(b[1]));
}
// SW128 swizzle for 128B rows
__device__ __forceinline__ uint32_t swz(uint32_t row, uint32_t colb) {
    return row * ROWB + (colb ^ ((row & 7u) << 4));
}

// ---------------------------------------------------------------------------
// Prologue 1: split x rows into 2 bf16 terms; A segments [a1, a2, a1]
// ---------------------------------------------------------------------------
__global__ void convert_x_kernel(const float* __restrict__ x) {
    int q = blockIdx.x, d = threadIdx.x;
    float v = x[(size_t)q * D_K + d];
    __nv_bfloat16 a1 = __float2bfloat16(v);
    float r1 = v - __bfloat162float(a1);
    __nv_bfloat16 a2 = __float2bfloat16(r1);
    __nv_bfloat16* A = g_A + (size_t)q * KP;
    A[0 * D_K + d] = a1; A[1 * D_K + d] = a2; A[2 * D_K + d] = a1;
}

// ---------------------------------------------------------------------------
// Prologue 2: split support rows; B segments [b1, b1, b2]; fused s2
// ---------------------------------------------------------------------------
__global__ void convert_s_kernel(const float* __restrict__ sup) {
    __shared__ float red[8];
    int n = blockIdx.x, d = threadIdx.x;
    float v = sup[(size_t)n * D_K + d];
    __nv_bfloat16 b1 = __float2bfloat16(v);
    float r1 = v - __bfloat162float(b1);
    __nv_bfloat16 b2 = __float2bfloat16(r1);
    __nv_bfloat16* Bp = g_B + (size_t)n * KP;
    Bp[0 * D_K + d] = b1; Bp[1 * D_K + d] = b1; Bp[2 * D_K + d] = b2;
    float s = v * v;
    #pragma unroll
    for (int off = 16; off > 0; off >>= 1) s += __shfl_down_sync(0xffffffffu, s, off);
    if ((d & 31) == 0) red[d >> 5] = s;
    __syncthreads();
    if (d == 0) {
        float t = 0.f;
        #pragma unroll
        for (int i = 0; i < 8; i++) t += red[i];
        g_s2[n] = t;
    }
}

// ---------------------------------------------------------------------------
// Main: HMMA GEMM M128 x N256 x K768 fused with argmin
// grid (GRID_N=128, GRID_M=16), 512 threads (16 warps, 4x4, warp tile 32x64)
// 4-stage cp.async pipeline, one barrier per K-chunk
// ---------------------------------------------------------------------------
__global__ __launch_bounds__(NTHREADS, 1)
void knn_mma_kernel() {
    extern __shared__ char smem[];
    const uint32_t sb = smem_u32(smem);
    __shared__ float s_s2[TILE_N];
    __shared__ float spv[TILE_M][4];
    __shared__ int   spi[TILE_M][4];

    const int tid = threadIdx.x, wid = tid >> 5, lane = tid & 31;
    const int warp_m = wid & 3, warp_n = wid >> 2;       // 4 x 4
    const int n0 = blockIdx.x * TILE_N, m0 = blockIdx.y * TILE_M;

    if (tid < TILE_N) s_s2[tid] = g_s2[n0 + tid];

    const char* gA = (const char*)g_A + (size_t)m0 * GROWB;
    const char* gB = (const char*)g_B + (size_t)n0 * GROWB;

    // -- async load of one K-chunk into stage buffer (A 16KB + B 32KB) --
    auto load_chunk = [&](int kc, int stg) {
        uint32_t sA = sb + stg * STAGE_BYTES;
        uint32_t sB = sA + A_STAGE;
        size_t colb = (size_t)kc * ROWB;
        #pragma unroll
        for (int i = 0; i < 2; i++) {            // A: 1024 x 16B granules
            int idx = tid + i * NTHREADS;
            int r = idx >> 3, p = (idx & 7) * 16;
            cp16(sA + swz(r, p), gA + (size_t)r * GROWB + colb + p);
        }
        #pragma unroll
        for (int i = 0; i < 4; i++) {            // B: 2048 x 16B granules
            int idx = tid + i * NTHREADS;
            int r = idx >> 3, p = (idx & 7) * 16;
            cp16(sB + swz(r, p), gB + (size_t)r * GROWB + colb + p);
        }
        cp_commit();
    };

    float acc[2][8][4];
    #pragma unroll
    for (int mt = 0; mt < 2; mt++)
        #pragma unroll
        for (int nb = 0; nb < 8; nb++)
            #pragma unroll
            for (int i = 0; i < 4; i++) acc[mt][nb][i] = 0.f;

    // per-lane fixed row/col pieces for ldmatrix addressing
    const uint32_t a_row = (uint32_t)(warp_m * 32 + (lane & 15));
    const uint32_t a_sub = (uint32_t)((lane >> 4) * 16);
    const uint32_t b_row = (uint32_t)(warp_n * 64 + (lane & 7) + ((lane >> 4) << 3));
    const uint32_t b_sub = (uint32_t)(((lane >> 3) & 1) * 16);

    load_chunk(0, 0);
    load_chunk(1, 1);
    load_chunk(2, 2);

    for (int k = 0; k < NKCH; k++) {
        // wait for chunk k's group: pending must drop to (commits - k - 1)
        if (k < NKCH - 2)      cp_wait<2>();
        else if (k == NKCH - 2) cp_wait<1>();
        else                    cp_wait<0>();
        __syncthreads();   // all warps past compute(k-1); stage (k+3)%4 reusable
        if (k + 3 < NKCH) load_chunk(k + 3, (k + 3) & 3);

        uint32_t sA = sb + (k & 3) * STAGE_BYTES;
        uint32_t sB = sA + A_STAGE;
        #pragma unroll
        for (int ks = 0; ks < 4; ks++) {
            uint32_t colA = (uint32_t)(ks * 32) + a_sub;
            uint32_t colB = (uint32_t)(ks * 32) + b_sub;
            uint32_t a[2][4], b[8][2];
            #pragma unroll
            for (int mt = 0; mt < 2; mt++)
                ldsm4(a[mt][0], a[mt][1], a[mt][2], a[mt][3],
                      sA + swz(a_row + mt * 16, colA));
            #pragma unroll
            for (int nb2 = 0; nb2 < 4; nb2++)
                ldsm4(b[nb2 * 2][0], b[nb2 * 2][1],
                      b[nb2 * 2 + 1][0], b[nb2 * 2 + 1][1],
                      sB + swz(b_row + nb2 * 16, colB));
            #pragma unroll
            for (int mt = 0; mt < 2; mt++)
                #pragma unroll
                for (int nb = 0; nb < 8; nb++)
                    mma16816(acc[mt][nb], a[mt], b[nb]);
        }
    }

    // -- fused epilogue: score = s2[n] - 2*dot, running argmin --
    float bv[2][2]; int bi[2][2];
    #pragma unroll
    for (int mt = 0; mt < 2; mt++)
        #pragma unroll
        for (int rh = 0; rh < 2; rh++) { bv[mt][rh] = FLT_MAX; bi[mt][rh] = 0; }

    #pragma unroll
    for (int mt = 0; mt < 2; mt++)
        #pragma unroll
        for (int rh = 0; rh < 2; rh++)
            #pragma unroll
            for (int nb = 0; nb < 8; nb++)
                #pragma unroll
                for (int c = 0; c < 2; c++) {
                    int col = warp_n * 64 + nb * 8 + 2 * (lane & 3) + c;
                    float sc = fmaf(-2.0f, acc[mt][nb][rh * 2 + c], s_s2[col]);
                    int n = n0 + col;
                    if (sc < bv[mt][rh]) { bv[mt][rh] = sc; bi[mt][rh] = n; }
                }

    // reduce across the 4 lanes sharing a row (lane bits 0-1 vary n)
    #pragma unroll
    for (int mt = 0; mt < 2; mt++)
        #pragma unroll
        for (int rh = 0; rh < 2; rh++) {
            float v = bv[mt][rh]; int ix = bi[mt][rh];
            #pragma unroll
            for (int msk = 1; msk <= 2; msk <<= 1) {
                float ov = __shfl_xor_sync(0xffffffffu, v, msk);
                int   oi = __shfl_xor_sync(0xffffffffu, ix, msk);
                if (ov < v || (ov == v && oi < ix)) { v = ov; ix = oi; }
            }
            if ((lane & 3) == 0) {
                int row = warp_m * 32 + mt * 16 + rh * 8 + (lane >> 2);
                spv[row][warp_n] = v;
                spi[row][warp_n] = ix;
            }
        }
    __syncthreads();

    if (tid < TILE_M) {
        float v = spv[tid][0]; int ix = spi[tid][0];
        #pragma unroll
        for (int t = 1; t < 4; t++) {
            float v2 = spv[tid][t]; int i2 = spi[tid][t];
            if (v2 < v || (v2 == v && i2 < ix)) { v = v2; ix = i2; }
        }
        g_pv[(size_t)(m0 + tid) * GRID_N + blockIdx.x] = v;
        g_pi[(size_t)(m0 + tid) * GRID_N + blockIdx.x] = ix;
    }
}

// ---------------------------------------------------------------------------
// Finalize: reduce GRID_N partials/query, gather label, write float one-hot
// ---------------------------------------------------------------------------
__global__ void finalize_kernel(const int* __restrict__ lab32,
                                float* __restrict__ out) {
    __shared__ float sv[GRID_N];
    __shared__ int   si[GRID_N];
    __shared__ int   s_lbl;
    const int b = blockIdx.x, t = threadIdx.x;
    sv[t] = g_pv[(size_t)b * GRID_N + t];
    si[t] = g_pi[(size_t)b * GRID_N + t];
    __syncthreads();
    #pragma unroll
    for (int s = GRID_N / 2; s > 0; s >>= 1) {
        if (t < s) {
            float v2 = sv[t + s]; int i2 = si[t + s];
            if (v2 < sv[t] || (v2 == sv[t] && i2 < si[t])) { sv[t] = v2; si[t] = i2; }
        }
        __syncthreads();
    }
    if (t == 0) {
        int bi = si[0];
        int hiOr = 0;                 // int64-vs-int32 label storage detection
        #pragma unroll
        for (int w = 1; w < 64; w += 2) hiOr |= lab32[w];
        s_lbl = (hiOr == 0) ? lab32[2 * bi] : lab32[bi];
    }
    __syncthreads();
    if (t < N_CLS) out[(size_t)b * N_CLS + t] = (t == s_lbl) ? 1.0f : 0.0f;
}

// ---------------------------------------------------------------------------
extern "C" void kernel_launch(void* const* d_in, const int* in_sizes, int n_in,
                              void* d_out, int out_size) {
    const float* x     = nullptr;
    const float* sup   = nullptr;
    const int*   lab32 = nullptr;
    for (int i = 0; i < n_in; i++) {
        long long sz = in_sizes[i];
        if (sz == 524288LL || sz == 2097152LL)         x     = (const float*)d_in[i];
        else if (sz == 8388608LL || sz == 33554432LL)  sup   = (const float*)d_in[i];
        else if (sz == 32768LL || sz == 65536LL ||
                 sz == 131072LL || sz == 262144LL)     lab32 = (const int*)d_in[i];
    }
    if (!x)     x     = (const float*)d_in[0];
    if (!sup)   sup   = (const float*)d_in[1];
    if (!lab32) lab32 = (const int*)d_in[2];
    float* out = (float*)d_out;

    static bool attr_set = false;
    if (!attr_set) {
        cudaFuncSetAttribute(knn_mma_kernel,
                             cudaFuncAttributeMaxDynamicSharedMemorySize,
                             STAGES * STAGE_BYTES);
        attr_set = true;
    }

    convert_x_kernel<<<B_Q, D_K>>>(x);
    convert_s_kernel<<<N_S, D_K>>>(sup);

    dim3 grid(GRID_N, GRID_M);   // 128 x 16
    knn_mma_kernel<<<grid, NTHREADS, STAGES * STAGE_BYTES>>>();

    finalize_kernel<<<B_Q, GRID_N>>>(lab32, out);
}